// round 4
// baseline (speedup 1.0000x reference)
#include <cuda_runtime.h>

#define H_IN   161
#define W_IN   161
#define C      128
#define H_OUT  641
#define W_OUT  641
#define NPIX   (H_OUT * W_OUT)
#define NEGV   (-1000000000.0f)

// Per-slot classification results (phase A -> phase B)
__device__ int      g_maskid[128];   // det_subset_index (cumsum(detected)-1)
__device__ int      g_sem[128];      // cls_pred (argmax class)
__device__ unsigned g_detmask[4];    // 128-bit detected mask
__device__ int      g_hasdet;

// ---------------------------------------------------------------------------
// Phase A: per-slot argmax/max over 133 classes, detection mask, cumsum.
// 1 block, 128 threads. Tiny.
// ---------------------------------------------------------------------------
__global__ void classify_kernel(const float* __restrict__ probs /*128x134*/) {
    __shared__ unsigned char sdet[128];
    int s = threadIdx.x;
    const float* row = probs + s * 134;
    float best = row[0];
    int bi = 0;
    for (int c = 1; c < 133; ++c) {
        float v = row[c];
        if (v > best) { best = v; bi = c; }   // strict > keeps first occurrence
    }
    g_sem[s] = bi;
    sdet[s] = (best >= 0.7f) ? 1 : 0;
    __syncthreads();
    if (s == 0) {
        int cum = 0;
        unsigned m[4] = {0u, 0u, 0u, 0u};
        for (int i = 0; i < 128; ++i) {
            if (sdet[i]) { m[i >> 5] |= 1u << (i & 31); cum++; }
            g_maskid[i] = cum - 1;
        }
        g_detmask[0] = m[0]; g_detmask[1] = m[1];
        g_detmask[2] = m[2]; g_detmask[3] = m[3];
        g_hasdet = (cum > 0) ? 1 : 0;
    }
}

// ---------------------------------------------------------------------------
// Phase B: one block per output row.
//  1) y-interp two input rows into SMEM rowbuf[161][128] (separable bilinear)
//  2) 4-thread quads: each quad owns a group of 4 consecutive output pixels
//     sharing the same (x0, x0+1) column pair. Each thread caches 32 channels
//     of both columns in registers, then for each sub-pixel does x-lerp,
//     full-max, detected-max+argmax (first-occurrence ties), and exp-sum.
// ---------------------------------------------------------------------------
extern __shared__ float rowbuf[];   // W_IN * C floats = 82432 bytes

__global__ void __launch_bounds__(256, 2)
postproc_kernel(const float* __restrict__ in, float* __restrict__ out) {
    const int y  = blockIdx.x;
    const int y0 = y >> 2;
    const int y1 = min(y0 + 1, H_IN - 1);
    const float wy   = (float)(y & 3) * 0.25f;
    const float omwy = 1.0f - wy;

    // ---- Phase 1: build y-interpolated row buffer ----
    {
        const float4* r0 = (const float4*)(in + (size_t)y0 * W_IN * C);
        const float4* r1 = (const float4*)(in + (size_t)y1 * W_IN * C);
        float4* rb = (float4*)rowbuf;
        const int NV = W_IN * C / 4;   // 5152
        if (wy == 0.0f) {
            for (int i = threadIdx.x; i < NV; i += 256) rb[i] = r0[i];
        } else {
            for (int i = threadIdx.x; i < NV; i += 256) {
                float4 a = r0[i], b = r1[i], t;
                t.x = a.x * omwy + b.x * wy;
                t.y = a.y * omwy + b.y * wy;
                t.z = a.z * omwy + b.z * wy;
                t.w = a.w * omwy + b.w * wy;
                rb[i] = t;
            }
        }
    }
    __syncthreads();

    const int lane = threadIdx.x & 31;
    const int q    = lane & 3;          // sub-thread in quad -> channel block
    const int c0   = q * 32;            // this thread's channel base
    const unsigned dword = g_detmask[q];
    const int hasdet = g_hasdet;
    const unsigned qmask = 0xFu << (lane & ~3);  // shfl member mask: own quad

    const int quad_global = threadIdx.x >> 2;    // 0..63

    // 161 column-groups: group g covers output x = 4g .. min(4g+3, 640)
    for (int g = quad_global; g <= 160; g += 64) {
        const int x0 = g;
        const int x1 = min(g + 1, W_IN - 1);

        float a[32], b[32];
        {
            const float4* pa = (const float4*)(rowbuf + x0 * C + c0);
            const float4* pb = (const float4*)(rowbuf + x1 * C + c0);
            #pragma unroll
            for (int i = 0; i < 8; ++i) {
                float4 va = pa[i];
                a[4*i+0] = va.x; a[4*i+1] = va.y; a[4*i+2] = va.z; a[4*i+3] = va.w;
                float4 vb = pb[i];
                b[4*i+0] = vb.x; b[4*i+1] = vb.y; b[4*i+2] = vb.z; b[4*i+3] = vb.w;
            }
        }

        const int nsub = (g == 160) ? 1 : 4;
        for (int sub = 0; sub < nsub; ++sub) {
            const float wx   = (float)sub * 0.25f;
            const float omwx = 1.0f - wx;

            // pass 1: full max + detected max/argmax over this thread's 32 ch
            float fm = -3.402823466e38f;
            float bv = -3.402823466e38f;
            int   bi = c0;
            #pragma unroll
            for (int c = 0; c < 32; ++c) {
                float v  = a[c] * omwx + b[c] * wx;
                fm = fmaxf(fm, v);
                float mv = ((dword >> c) & 1u) ? v : NEGV;
                if (mv > bv) { bv = mv; bi = c0 + c; }   // strict >: first occurrence
            }
            // quad reduction (lanes l^1, l^2 are in the same quad)
            #pragma unroll
            for (int off = 1; off <= 2; off <<= 1) {
                float ofm = __shfl_xor_sync(qmask, fm, off);
                float obv = __shfl_xor_sync(qmask, bv, off);
                int   obi = __shfl_xor_sync(qmask, bi, off);
                fm = fmaxf(fm, ofm);
                if (obv > bv || (obv == bv && obi < bi)) { bv = obv; bi = obi; }
            }

            // pass 2: sum exp(masked - det_max); undetected -> exp(NEG-bv) = 0
            float s = 0.0f;
            #pragma unroll
            for (int c = 0; c < 32; ++c) {
                float v  = a[c] * omwx + b[c] * wx;
                float mv = ((dword >> c) & 1u) ? v : NEGV;
                s += __expf(mv - bv);
            }
            #pragma unroll
            for (int off = 1; off <= 2; off <<= 1)
                s += __shfl_xor_sync(qmask, s, off);

            if (q == 0) {
                const int x = 4 * g + sub;
                const int p = y * W_OUT + x;
                float maskid, sem, thing, stuff;
                if (hasdet) {
                    // pixel_conf > 0.4  <=>  1/s > 0.4  <=>  s < 2.5
                    float cf = (s < 2.5f && fm == bv) ? 1.0f : 0.0f;
                    int semI = g_sem[bi];
                    maskid = (float)(g_maskid[bi] + 1);
                    sem    = (float)semI;              // THING_STUFF_IDS == identity
                    thing  = (semI < 80)  ? cf : 0.0f;
                    stuff  = (semI >= 80) ? cf : 0.0f;
                } else {
                    maskid = 1.0f; sem = 0.0f; thing = 0.0f; stuff = 0.0f;
                }
                out[p]            = maskid;
                out[NPIX + p]     = sem;
                out[2 * NPIX + p] = thing;
                out[3 * NPIX + p] = stuff;
            }
        }
    }
}

// ---------------------------------------------------------------------------
extern "C" void kernel_launch(void* const* d_in, const int* in_sizes, int n_in,
                              void* d_out, int out_size) {
    const float* logits = (const float*)d_in[0];  // (161,161,128)
    const float* probs  = (const float*)d_in[1];  // (128,134)
    if (n_in >= 2 && in_sizes[0] < in_sizes[1]) { // safety: order by size
        const float* t = logits; logits = probs; probs = t;
    }
    float* out = (float*)d_out;

    static int smem_set = 0;
    const int smem_bytes = W_IN * C * sizeof(float);  // 82432
    if (!smem_set) {
        cudaFuncSetAttribute(postproc_kernel,
                             cudaFuncAttributeMaxDynamicSharedMemorySize,
                             smem_bytes);
        smem_set = 1;
    }

    classify_kernel<<<1, 128>>>(probs);
    postproc_kernel<<<H_OUT, 256, smem_bytes>>>(logits, out);
}

// round 5
// speedup vs baseline: 1.0627x; 1.0627x over previous
#include <cuda_runtime.h>

#define H_IN   161
#define W_IN   161
#define C      128
#define H_OUT  641
#define W_OUT  641
#define NPIX   (H_OUT * W_OUT)
#define NEGV   (-1000000000.0f)

// Per-slot classification results (phase A -> phase B)
__device__ int      g_maskid[128];   // det_subset_index (cumsum(detected)-1)
__device__ int      g_sem[128];      // cls_pred (argmax class)
__device__ unsigned g_detmask[4];    // 128-bit detected mask
__device__ int      g_hasdet;

// ---------------------------------------------------------------------------
// Phase A: per-slot argmax/max over 133 classes, detection mask, cumsum.
// 1 block, 128 threads. Tiny.
// ---------------------------------------------------------------------------
__global__ void classify_kernel(const float* __restrict__ probs /*128x134*/) {
    __shared__ unsigned char sdet[128];
    int s = threadIdx.x;
    const float* row = probs + s * 134;
    float best = row[0];
    int bi = 0;
    for (int c = 1; c < 133; ++c) {
        float v = row[c];
        if (v > best) { best = v; bi = c; }   // strict > keeps first occurrence
    }
    g_sem[s] = bi;
    sdet[s] = (best >= 0.7f) ? 1 : 0;
    __syncthreads();
    if (s == 0) {
        int cum = 0;
        unsigned m[4] = {0u, 0u, 0u, 0u};
        for (int i = 0; i < 128; ++i) {
            if (sdet[i]) { m[i >> 5] |= 1u << (i & 31); cum++; }
            g_maskid[i] = cum - 1;
        }
        g_detmask[0] = m[0]; g_detmask[1] = m[1];
        g_detmask[2] = m[2]; g_detmask[3] = m[3];
        g_hasdet = (cum > 0) ? 1 : 0;
    }
}

// ---------------------------------------------------------------------------
// Phase B: one block per output row.
//  1) y-interp two input rows into SMEM rowbuf[161][128] (separable bilinear)
//  2) 4-thread quads: each quad owns a group of 4 consecutive output pixels
//     sharing the same (x0, x0+1) column pair. Each thread caches 32 channels
//     of both columns in registers, then for each sub-pixel does x-lerp,
//     full-max, detected-max+argmax (first-occurrence ties), and exp-sum.
// ---------------------------------------------------------------------------
extern __shared__ float rowbuf[];   // W_IN * C floats = 82432 bytes

__global__ void __launch_bounds__(256, 2)
postproc_kernel(const float* __restrict__ in, float* __restrict__ out) {
    const int y  = blockIdx.x;
    const int y0 = y >> 2;
    const int y1 = min(y0 + 1, H_IN - 1);
    const float wy   = (float)(y & 3) * 0.25f;
    const float omwy = 1.0f - wy;

    // ---- Phase 1: build y-interpolated row buffer ----
    {
        const float4* r0 = (const float4*)(in + (size_t)y0 * W_IN * C);
        const float4* r1 = (const float4*)(in + (size_t)y1 * W_IN * C);
        float4* rb = (float4*)rowbuf;
        const int NV = W_IN * C / 4;   // 5152
        if (wy == 0.0f) {
            for (int i = threadIdx.x; i < NV; i += 256) rb[i] = r0[i];
        } else {
            for (int i = threadIdx.x; i < NV; i += 256) {
                float4 a = r0[i], b = r1[i], t;
                t.x = a.x * omwy + b.x * wy;
                t.y = a.y * omwy + b.y * wy;
                t.z = a.z * omwy + b.z * wy;
                t.w = a.w * omwy + b.w * wy;
                rb[i] = t;
            }
        }
    }
    __syncthreads();

    const int lane = threadIdx.x & 31;
    const int q    = lane & 3;          // sub-thread in quad -> channel block
    const int c0   = q * 32;            // this thread's channel base
    const unsigned dword = g_detmask[q];
    const int hasdet = g_hasdet;
    const unsigned qmask = 0xFu << (lane & ~3);  // shfl member mask: own quad

    const int quad_global = threadIdx.x >> 2;    // 0..63

    // 161 column-groups: group g covers output x = 4g .. min(4g+3, 640)
    for (int g = quad_global; g <= 160; g += 64) {
        const int x0 = g;
        const int x1 = min(g + 1, W_IN - 1);

        float a[32], b[32];
        {
            const float4* pa = (const float4*)(rowbuf + x0 * C + c0);
            const float4* pb = (const float4*)(rowbuf + x1 * C + c0);
            #pragma unroll
            for (int i = 0; i < 8; ++i) {
                float4 va = pa[i];
                a[4*i+0] = va.x; a[4*i+1] = va.y; a[4*i+2] = va.z; a[4*i+3] = va.w;
                float4 vb = pb[i];
                b[4*i+0] = vb.x; b[4*i+1] = vb.y; b[4*i+2] = vb.z; b[4*i+3] = vb.w;
            }
        }

        const int nsub = (g == 160) ? 1 : 4;
        for (int sub = 0; sub < nsub; ++sub) {
            const float wx   = (float)sub * 0.25f;
            const float omwx = 1.0f - wx;

            // pass 1: full max + detected max/argmax over this thread's 32 ch
            float fm = -3.402823466e38f;
            float bv = -3.402823466e38f;
            int   bi = c0;
            #pragma unroll
            for (int c = 0; c < 32; ++c) {
                float v  = a[c] * omwx + b[c] * wx;
                fm = fmaxf(fm, v);
                float mv = ((dword >> c) & 1u) ? v : NEGV;
                if (mv > bv) { bv = mv; bi = c0 + c; }   // strict >: first occurrence
            }
            // quad reduction (lanes l^1, l^2 are in the same quad)
            #pragma unroll
            for (int off = 1; off <= 2; off <<= 1) {
                float ofm = __shfl_xor_sync(qmask, fm, off);
                float obv = __shfl_xor_sync(qmask, bv, off);
                int   obi = __shfl_xor_sync(qmask, bi, off);
                fm = fmaxf(fm, ofm);
                if (obv > bv || (obv == bv && obi < bi)) { bv = obv; bi = obi; }
            }

            // pass 2: sum exp(masked - det_max); undetected -> exp(NEG-bv) = 0
            float s = 0.0f;
            #pragma unroll
            for (int c = 0; c < 32; ++c) {
                float v  = a[c] * omwx + b[c] * wx;
                float mv = ((dword >> c) & 1u) ? v : NEGV;
                s += __expf(mv - bv);
            }
            #pragma unroll
            for (int off = 1; off <= 2; off <<= 1)
                s += __shfl_xor_sync(qmask, s, off);

            if (q == 0) {
                const int x = 4 * g + sub;
                const int p = y * W_OUT + x;
                float maskid, sem, thing, stuff;
                if (hasdet) {
                    // pixel_conf > 0.4  <=>  1/s > 0.4  <=>  s < 2.5
                    float cf = (s < 2.5f && fm == bv) ? 1.0f : 0.0f;
                    int semI = g_sem[bi];
                    maskid = (float)(g_maskid[bi] + 1);
                    sem    = (float)semI;              // THING_STUFF_IDS == identity
                    thing  = (semI < 80)  ? cf : 0.0f;
                    stuff  = (semI >= 80) ? cf : 0.0f;
                } else {
                    maskid = 1.0f; sem = 0.0f; thing = 0.0f; stuff = 0.0f;
                }
                out[p]            = maskid;
                out[NPIX + p]     = sem;
                out[2 * NPIX + p] = thing;
                out[3 * NPIX + p] = stuff;
            }
        }
    }
}

// ---------------------------------------------------------------------------
extern "C" void kernel_launch(void* const* d_in, const int* in_sizes, int n_in,
                              void* d_out, int out_size) {
    const float* logits = (const float*)d_in[0];  // (161,161,128)
    const float* probs  = (const float*)d_in[1];  // (128,134)
    if (n_in >= 2 && in_sizes[0] < in_sizes[1]) { // safety: order by size
        const float* t = logits; logits = probs; probs = t;
    }
    float* out = (float*)d_out;

    static int smem_set = 0;
    const int smem_bytes = W_IN * C * sizeof(float);  // 82432
    if (!smem_set) {
        cudaFuncSetAttribute(postproc_kernel,
                             cudaFuncAttributeMaxDynamicSharedMemorySize,
                             smem_bytes);
        smem_set = 1;
    }

    classify_kernel<<<1, 128>>>(probs);
    postproc_kernel<<<H_OUT, 256, smem_bytes>>>(logits, out);
}